// round 1
// baseline (speedup 1.0000x reference)
#include <cuda_runtime.h>
#include <math.h>

// Problem constants
#define Bsz 2
#define Tt 2048
#define Cc 1024
#define Hh 16
#define HD 64
#define NTOK (Bsz*Tt)   // 4096
#define C3 (3*Cc)       // 3072
#define KEEP_INV (1.0f/0.9f)
#define SQ 65           // padded smem row stride for attention tiles

// Scratch (allocation-free requirement: device globals)
__device__ float g_q[(size_t)Bsz*Hh*Tt*HD];
__device__ float g_k[(size_t)Bsz*Hh*Tt*HD];
__device__ float g_v[(size_t)Bsz*Hh*Tt*HD];
__device__ float g_y[(size_t)NTOK*Cc];

// ---------------------------------------------------------------------------
// QKV GEMM: X[4096,1024] @ Wqkv[1024,3072] + bqkv, scattered into q/k/v
// laid out [B,H,T,HD].
// ---------------------------------------------------------------------------
__global__ __launch_bounds__(256) void qkv_gemm(const float* __restrict__ X,
                                                const float* __restrict__ W,
                                                const float* __restrict__ bias) {
    __shared__ float As[8][128];
    __shared__ float Bs[8][128];
    int tid = threadIdx.x;
    int br = blockIdx.y;   // M block
    int bc = blockIdx.x;   // N block

    int a_row = tid >> 1;
    int a_col = (tid & 1) * 4;
    int b_row = tid >> 5;
    int b_col = (tid & 31) * 4;
    int tr = tid >> 4, tc = tid & 15;

    const float* Xa = X + (size_t)(br*128 + a_row)*Cc + a_col;
    const float* Wb = W + (size_t)b_row*C3 + bc*128 + b_col;

    float acc[8][8] = {};
    float4 av = *(const float4*)(Xa);
    float4 bv = *(const float4*)(Wb);

    for (int kt = 0; kt < Cc; kt += 8) {
        As[a_col+0][a_row] = av.x; As[a_col+1][a_row] = av.y;
        As[a_col+2][a_row] = av.z; As[a_col+3][a_row] = av.w;
        *(float4*)&Bs[b_row][b_col] = bv;
        __syncthreads();

        float4 av2 = av, bv2 = bv;
        if (kt + 8 < Cc) {
            av2 = *(const float4*)(Xa + kt + 8);
            bv2 = *(const float4*)(Wb + (size_t)(kt+8)*C3);
        }
        #pragma unroll
        for (int k = 0; k < 8; ++k) {
            float ra[8], rb[8];
            *(float4*)(ra)   = *(const float4*)&As[k][tr*8];
            *(float4*)(ra+4) = *(const float4*)&As[k][tr*8+4];
            *(float4*)(rb)   = *(const float4*)&Bs[k][tc*8];
            *(float4*)(rb+4) = *(const float4*)&Bs[k][tc*8+4];
            #pragma unroll
            for (int i = 0; i < 8; ++i)
                #pragma unroll
                for (int j = 0; j < 8; ++j)
                    acc[i][j] = fmaf(ra[i], rb[j], acc[i][j]);
        }
        __syncthreads();
        av = av2; bv = bv2;
    }

    // Scatter epilogue: split 3C into q/k/v, layout [B,H,T,HD]
    #pragma unroll
    for (int i = 0; i < 8; ++i) {
        int n = br*128 + tr*8 + i;
        int b = n >> 11, t = n & (Tt-1);
        #pragma unroll
        for (int j = 0; j < 8; ++j) {
            int col = bc*128 + tc*8 + j;
            float v = acc[i][j] + bias[col];
            int which = col >> 10;
            int cidx = col & 1023;
            int h = cidx >> 6, d = cidx & 63;
            float* dst = (which == 0) ? g_q : (which == 1) ? g_k : g_v;
            dst[(((size_t)(b*Hh + h))*Tt + t)*HD + d] = v;
        }
    }
}

// ---------------------------------------------------------------------------
// Flash-style causal attention with attention-dropout keep-mask.
// Softmax denominator uses UNDROPPED probabilities; numerator uses
// dropped/scaled ones (matches reference exactly, no renormalization).
// One block = 64 query rows of one (b,h). 256 threads, 4x4 microtiles.
// ---------------------------------------------------------------------------
__global__ __launch_bounds__(256) void flash_attn(const unsigned* __restrict__ amask) {
    extern __shared__ float sm[];
    float* Qs = sm;              // [64][SQ]
    float* Ks = Qs + 64*SQ;
    float* Vs = Ks + 64*SQ;
    float* Ss = Vs + 64*SQ;
    float* m_s  = Ss + 64*SQ;    // [64]
    float* l_s  = m_s + 64;
    float* al_s = l_s + 64;

    int tid = threadIdx.x;
    int bh = blockIdx.y;
    int qb = blockIdx.x;
    int q0 = qb * 64;
    const float* Qg = g_q + (size_t)bh*Tt*HD;
    const float* Kg = g_k + (size_t)bh*Tt*HD;
    const float* Vg = g_v + (size_t)bh*Tt*HD;

    // Load Q tile, pre-scaled by 1/sqrt(hd)
    for (int i = tid; i < 1024; i += 256) {
        int r = i >> 4, c = (i & 15) * 4;
        float4 v = *(const float4*)(Qg + (size_t)(q0 + r)*HD + c);
        Qs[r*SQ+c]   = v.x*0.125f; Qs[r*SQ+c+1] = v.y*0.125f;
        Qs[r*SQ+c+2] = v.z*0.125f; Qs[r*SQ+c+3] = v.w*0.125f;
    }
    if (tid < 64) { m_s[tid] = -INFINITY; l_s[tid] = 0.f; }

    int tr = tid >> 4, tc = tid & 15;
    float acc[4][4] = {};

    for (int kt = 0; kt <= qb; ++kt) {
        int k0 = kt * 64;
        __syncthreads();   // protect Ks/Vs/Ss from previous iteration
        for (int i = tid; i < 1024; i += 256) {
            int r = i >> 4, c = (i & 15) * 4;
            float4 kv = *(const float4*)(Kg + (size_t)(k0 + r)*HD + c);
            Ks[r*SQ+c] = kv.x; Ks[r*SQ+c+1] = kv.y; Ks[r*SQ+c+2] = kv.z; Ks[r*SQ+c+3] = kv.w;
            float4 vv = *(const float4*)(Vg + (size_t)(k0 + r)*HD + c);
            Vs[r*SQ+c] = vv.x; Vs[r*SQ+c+1] = vv.y; Vs[r*SQ+c+2] = vv.z; Vs[r*SQ+c+3] = vv.w;
        }
        __syncthreads();

        // S = Q K^T (scaled), causal mask
        float s[4][4] = {};
        #pragma unroll 8
        for (int d = 0; d < 64; ++d) {
            float a[4], bb[4];
            #pragma unroll
            for (int ii = 0; ii < 4; ++ii) a[ii]  = Qs[(tr*4+ii)*SQ + d];
            #pragma unroll
            for (int jj = 0; jj < 4; ++jj) bb[jj] = Ks[(tc*4+jj)*SQ + d];
            #pragma unroll
            for (int ii = 0; ii < 4; ++ii)
                #pragma unroll
                for (int jj = 0; jj < 4; ++jj)
                    s[ii][jj] = fmaf(a[ii], bb[jj], s[ii][jj]);
        }
        #pragma unroll
        for (int ii = 0; ii < 4; ++ii)
            #pragma unroll
            for (int jj = 0; jj < 4; ++jj) {
                float v = s[ii][jj];
                if (q0 + tr*4 + ii < k0 + tc*4 + jj) v = -INFINITY;
                Ss[(tr*4+ii)*SQ + tc*4+jj] = v;
            }
        __syncthreads();

        // Online softmax + dropout (one thread per query row)
        if (tid < 64) {
            int i = tid;
            float mo = m_s[i];
            float mx = mo;
            #pragma unroll 8
            for (int j = 0; j < 64; ++j) mx = fmaxf(mx, Ss[i*SQ+j]);
            float al = __expf(mo - mx);
            const unsigned* mrow = amask + ((size_t)bh*Tt + (q0+i))*Tt + k0;
            float sum = 0.f;
            #pragma unroll 8
            for (int j = 0; j < 64; ++j) {
                float p = __expf(Ss[i*SQ+j] - mx);
                sum += p;                                  // undropped denominator
                Ss[i*SQ+j] = mrow[j] ? p*KEEP_INV : 0.f;   // dropped numerator
            }
            m_s[i] = mx;
            l_s[i] = fmaf(l_s[i], al, sum);
            al_s[i] = al;
        }
        __syncthreads();

        // acc = acc*alpha + P @ V
        #pragma unroll
        for (int ii = 0; ii < 4; ++ii) {
            float a = al_s[tr*4+ii];
            #pragma unroll
            for (int dd = 0; dd < 4; ++dd) acc[ii][dd] *= a;
        }
        #pragma unroll 4
        for (int j = 0; j < 64; ++j) {
            float p[4], vv[4];
            #pragma unroll
            for (int ii = 0; ii < 4; ++ii) p[ii]  = Ss[(tr*4+ii)*SQ + j];
            #pragma unroll
            for (int dd = 0; dd < 4; ++dd) vv[dd] = Vs[j*SQ + tc*4+dd];
            #pragma unroll
            for (int ii = 0; ii < 4; ++ii)
                #pragma unroll
                for (int dd = 0; dd < 4; ++dd)
                    acc[ii][dd] = fmaf(p[ii], vv[dd], acc[ii][dd]);
        }
    }

    // y = acc / l, regathered to [B,T,C]
    int b = bh >> 4, h = bh & 15;
    #pragma unroll
    for (int ii = 0; ii < 4; ++ii) {
        int qi = q0 + tr*4 + ii;
        float inv = 1.f / l_s[tr*4+ii];
        #pragma unroll
        for (int dd = 0; dd < 4; ++dd)
            g_y[((size_t)(b*Tt) + qi)*Cc + h*HD + tc*4+dd] = acc[ii][dd]*inv;
    }
}

// ---------------------------------------------------------------------------
// Proj GEMM: y[4096,1024] @ Wproj[1024,1024] + bproj, fused resid dropout.
// ---------------------------------------------------------------------------
__global__ __launch_bounds__(256) void proj_gemm(const float* __restrict__ W,
                                                 const float* __restrict__ bias,
                                                 const unsigned* __restrict__ rmask,
                                                 float* __restrict__ out) {
    __shared__ float As[8][128];
    __shared__ float Bs[8][128];
    int tid = threadIdx.x;
    int br = blockIdx.y;
    int bc = blockIdx.x;

    int a_row = tid >> 1;
    int a_col = (tid & 1) * 4;
    int b_row = tid >> 5;
    int b_col = (tid & 31) * 4;
    int tr = tid >> 4, tc = tid & 15;

    const float* Xa = g_y + (size_t)(br*128 + a_row)*Cc + a_col;
    const float* Wb = W + (size_t)b_row*Cc + bc*128 + b_col;

    float acc[8][8] = {};
    float4 av = *(const float4*)(Xa);
    float4 bv = *(const float4*)(Wb);

    for (int kt = 0; kt < Cc; kt += 8) {
        As[a_col+0][a_row] = av.x; As[a_col+1][a_row] = av.y;
        As[a_col+2][a_row] = av.z; As[a_col+3][a_row] = av.w;
        *(float4*)&Bs[b_row][b_col] = bv;
        __syncthreads();

        float4 av2 = av, bv2 = bv;
        if (kt + 8 < Cc) {
            av2 = *(const float4*)(Xa + kt + 8);
            bv2 = *(const float4*)(Wb + (size_t)(kt+8)*Cc);
        }
        #pragma unroll
        for (int k = 0; k < 8; ++k) {
            float ra[8], rb[8];
            *(float4*)(ra)   = *(const float4*)&As[k][tr*8];
            *(float4*)(ra+4) = *(const float4*)&As[k][tr*8+4];
            *(float4*)(rb)   = *(const float4*)&Bs[k][tc*8];
            *(float4*)(rb+4) = *(const float4*)&Bs[k][tc*8+4];
            #pragma unroll
            for (int i = 0; i < 8; ++i)
                #pragma unroll
                for (int j = 0; j < 8; ++j)
                    acc[i][j] = fmaf(ra[i], rb[j], acc[i][j]);
        }
        __syncthreads();
        av = av2; bv = bv2;
    }

    #pragma unroll
    for (int i = 0; i < 8; ++i) {
        int n = br*128 + tr*8 + i;
        #pragma unroll
        for (int j = 0; j < 8; ++j) {
            int col = bc*128 + tc*8 + j;
            float v = acc[i][j] + bias[col];
            size_t idx = (size_t)n*Cc + col;
            out[idx] = rmask[idx] ? v*KEEP_INV : 0.f;
        }
    }
}

// ---------------------------------------------------------------------------
extern "C" void kernel_launch(void* const* d_in, const int* in_sizes, int n_in,
                              void* d_out, int out_size) {
    const float* x     = (const float*)d_in[0];
    const float* Wqkv  = (const float*)d_in[1];
    const float* bqkv  = (const float*)d_in[2];
    const float* Wproj = (const float*)d_in[3];
    const float* bproj = (const float*)d_in[4];
    const unsigned* amask = (const unsigned*)d_in[5];
    const unsigned* rmask = (const unsigned*)d_in[6];
    float* out = (float*)d_out;

    qkv_gemm<<<dim3(C3/128, NTOK/128), 256>>>(x, Wqkv, bqkv);

    size_t shm = (size_t)(4*64*SQ + 3*64) * sizeof(float);  // 67328 B
    cudaFuncSetAttribute(flash_attn, cudaFuncAttributeMaxDynamicSharedMemorySize, (int)shm);
    flash_attn<<<dim3(Tt/64, Bsz*Hh), 256, shm>>>(amask);

    proj_gemm<<<dim3(Cc/128, NTOK/128), 256>>>(Wproj, bproj, rmask, out);
}

// round 3
// speedup vs baseline: 1.5302x; 1.5302x over previous
#include <cuda_runtime.h>
#include <cuda_bf16.h>
#include <math.h>
#include <cstdint>

// Problem constants
#define Bsz 2
#define Tt 2048
#define Cc 1024
#define Hh 16
#define HD 64
#define NTOK (Bsz*Tt)   // 4096
#define C3 (3*Cc)       // 3072
#define KEEP_INV (1.0f/0.9f)
#define SQ 65

// ---------------- scratch (device globals; no allocs allowed) ---------------
__device__ float g_q[(size_t)Bsz*Hh*Tt*HD];
__device__ float g_k[(size_t)Bsz*Hh*Tt*HD];
__device__ float g_v[(size_t)Bsz*Hh*Tt*HD];
__device__ float g_y[(size_t)NTOK*Cc];

__device__ __nv_bfloat16 g_xh[(size_t)NTOK*Cc],  g_xl[(size_t)NTOK*Cc];
__device__ __nv_bfloat16 g_wqh[(size_t)C3*Cc],   g_wql[(size_t)C3*Cc];   // [N,K]
__device__ __nv_bfloat16 g_wph[(size_t)Cc*Cc],   g_wpl[(size_t)Cc*Cc];   // [N,K]
__device__ __nv_bfloat16 g_yh[(size_t)NTOK*Cc],  g_yl[(size_t)NTOK*Cc];

// ---------------- helpers ----------------
__device__ __forceinline__ uint32_t smem_u32(const void* p) {
    uint32_t a;
    asm("{ .reg .u64 t; cvta.to.shared.u64 t, %1; cvt.u32.u64 %0, t; }" : "=r"(a) : "l"(p));
    return a;
}
__device__ __forceinline__ void cp_async16(uint32_t dst, const void* src) {
    asm volatile("cp.async.cg.shared.global [%0], [%1], 16;" :: "r"(dst), "l"(src) : "memory");
}
#define CP_COMMIT() asm volatile("cp.async.commit_group;" ::: "memory")
#define CP_WAIT(n)  asm volatile("cp.async.wait_group %0;" :: "n"(n) : "memory")

__device__ __forceinline__ void mma16816(float* c, const uint32_t* a, const uint32_t* b) {
    asm volatile("mma.sync.aligned.m16n8k16.row.col.f32.bf16.bf16.f32 "
        "{%0,%1,%2,%3}, {%4,%5,%6,%7}, {%8,%9}, {%0,%1,%2,%3};"
        : "+f"(c[0]), "+f"(c[1]), "+f"(c[2]), "+f"(c[3])
        : "r"(a[0]), "r"(a[1]), "r"(a[2]), "r"(a[3]), "r"(b[0]), "r"(b[1]));
}

// ---------------------------------------------------------------------------
// fp32 -> (hi,lo) bf16 split
// ---------------------------------------------------------------------------
__global__ __launch_bounds__(256) void cvt_split(const float4* __restrict__ in,
                                                 __nv_bfloat162* __restrict__ hi,
                                                 __nv_bfloat162* __restrict__ lo,
                                                 int n4) {
    int i = blockIdx.x * 256 + threadIdx.x;
    if (i >= n4) return;
    float4 v = in[i];
    __nv_bfloat16 hx = __float2bfloat16(v.x), hy = __float2bfloat16(v.y);
    __nv_bfloat16 hz = __float2bfloat16(v.z), hw = __float2bfloat16(v.w);
    hi[2*i]   = __nv_bfloat162(hx, hy);
    hi[2*i+1] = __nv_bfloat162(hz, hw);
    lo[2*i]   = __nv_bfloat162(__float2bfloat16(v.x - __bfloat162float(hx)),
                               __float2bfloat16(v.y - __bfloat162float(hy)));
    lo[2*i+1] = __nv_bfloat162(__float2bfloat16(v.z - __bfloat162float(hz)),
                               __float2bfloat16(v.w - __bfloat162float(hw)));
}

// fp32 W[K,N] -> transposed split bf16 [N,K]
__global__ __launch_bounds__(256) void cvt_split_T(const float* __restrict__ in,
                                                   __nv_bfloat16* __restrict__ hi,
                                                   __nv_bfloat16* __restrict__ lo,
                                                   int K, int N) {
    __shared__ float t[32][33];
    int nx = blockIdx.x * 32, kx = blockIdx.y * 32;
    int tx = threadIdx.x, ty = threadIdx.y;  // (32,8)
    #pragma unroll
    for (int r = 0; r < 4; ++r)
        t[ty + 8*r][tx] = in[(size_t)(kx + ty + 8*r) * N + nx + tx];
    __syncthreads();
    #pragma unroll
    for (int r = 0; r < 4; ++r) {
        float v = t[tx][ty + 8*r];
        size_t o = (size_t)(nx + ty + 8*r) * K + kx + tx;
        __nv_bfloat16 h = __float2bfloat16(v);
        hi[o] = h;
        lo[o] = __float2bfloat16(v - __bfloat162float(h));
    }
}

// ---------------------------------------------------------------------------
// mma.sync split-bf16 GEMM: C[M,N] = A[M,K] * B[N,K]^T  (+bias, +epilogue)
// Block tile 128x128, K-chunk 32, 8 warps (4x2), warp tile 32x64.
// Smem rows padded to 40 bf16 (80B) -> conflict-free fragment LDS.
// MODE 0: qkv scatter into g_q/g_k/g_v.  MODE 1: proj + resid dropout -> out.
// ---------------------------------------------------------------------------
#define SR 40                   // smem row stride in bf16 elems
#define TILE_E (128*SR)         // 5120 elems per tile
#define BUF_E  (4*TILE_E)       // Ah,Al,Bh,Bl
#define GEMM_SMEM (2*BUF_E*2)   // bytes = 81920

template<int MODE>
__device__ __forceinline__ void gemm_issue(uint32_t sb, int buf,
                                           const __nv_bfloat16* Ah, const __nv_bfloat16* Al,
                                           const __nv_bfloat16* Bh, const __nv_bfloat16* Bl,
                                           int m0, int n0, int K, int ch, int tid) {
    #pragma unroll
    for (int it = 0; it < 8; ++it) {
        int u = tid + it * 256;           // 0..2047
        int arr = u >> 9;                 // tile 0..3
        int rem = u & 511;
        int row = rem >> 2;
        int c16 = rem & 3;                // 16B unit (8 bf16)
        const __nv_bfloat16* src = (arr == 0) ? Ah : (arr == 1) ? Al : (arr == 2) ? Bh : Bl;
        int grow = (arr < 2 ? m0 : n0) + row;
        uint32_t soff = (uint32_t)((buf * BUF_E + arr * TILE_E + row * SR + c16 * 8) * 2);
        cp_async16(sb + soff, src + (size_t)grow * K + ch * 32 + c16 * 8);
    }
    CP_COMMIT();
}

template<int MODE>
__global__ __launch_bounds__(256) void gemm_mma(const __nv_bfloat16* __restrict__ Ah,
                                                const __nv_bfloat16* __restrict__ Al,
                                                const __nv_bfloat16* __restrict__ Bh,
                                                const __nv_bfloat16* __restrict__ Bl,
                                                const float* __restrict__ bias,
                                                const unsigned* __restrict__ rmask,
                                                float* __restrict__ out,
                                                int K) {
    extern __shared__ __nv_bfloat16 smg[];
    uint32_t sb = smem_u32(smg);
    int tid = threadIdx.x, wid = tid >> 5, lane = tid & 31;
    int m0 = blockIdx.y * 128, n0 = blockIdx.x * 128;
    int wm = (wid & 3) * 32, wn = (wid >> 2) * 64;
    int qr = lane >> 2, qc = lane & 3;

    float acc[2][8][4] = {};
    int nch = K >> 5;

    gemm_issue<MODE>(sb, 0, Ah, Al, Bh, Bl, m0, n0, K, 0, tid);

    for (int ch = 0; ch < nch; ++ch) {
        int buf = ch & 1;
        if (ch + 1 < nch) {
            gemm_issue<MODE>(sb, buf ^ 1, Ah, Al, Bh, Bl, m0, n0, K, ch + 1, tid);
            CP_WAIT(1);
        } else {
            CP_WAIT(0);
        }
        __syncthreads();

        const __nv_bfloat16* sAh = smg + buf * BUF_E;
        const __nv_bfloat16* sAl = sAh + TILE_E;
        const __nv_bfloat16* sBh = sAl + TILE_E;
        const __nv_bfloat16* sBl = sBh + TILE_E;

        #pragma unroll
        for (int ks = 0; ks < 32; ks += 16) {
            uint32_t ah[2][4], al_[2][4];
            #pragma unroll
            for (int i = 0; i < 2; ++i) {
                int r = wm + i * 16 + qr;
                int c = ks + qc * 2;
                ah[i][0]  = *(const uint32_t*)&sAh[r*SR + c];
                ah[i][1]  = *(const uint32_t*)&sAh[(r+8)*SR + c];
                ah[i][2]  = *(const uint32_t*)&sAh[r*SR + c + 8];
                ah[i][3]  = *(const uint32_t*)&sAh[(r+8)*SR + c + 8];
                al_[i][0] = *(const uint32_t*)&sAl[r*SR + c];
                al_[i][1] = *(const uint32_t*)&sAl[(r+8)*SR + c];
                al_[i][2] = *(const uint32_t*)&sAl[r*SR + c + 8];
                al_[i][3] = *(const uint32_t*)&sAl[(r+8)*SR + c + 8];
            }
            #pragma unroll
            for (int j = 0; j < 8; ++j) {
                int n = wn + j * 8 + qr;
                int c = ks + qc * 2;
                uint32_t bh[2], bl[2];
                bh[0] = *(const uint32_t*)&sBh[n*SR + c];
                bh[1] = *(const uint32_t*)&sBh[n*SR + c + 8];
                bl[0] = *(const uint32_t*)&sBl[n*SR + c];
                bl[1] = *(const uint32_t*)&sBl[n*SR + c + 8];
                #pragma unroll
                for (int i = 0; i < 2; ++i) {
                    mma16816(acc[i][j], ah[i], bh);   // Ah*Bh
                    mma16816(acc[i][j], ah[i], bl);   // Ah*Bl
                    mma16816(acc[i][j], al_[i], bh);  // Al*Bh
                }
            }
        }
        __syncthreads();
    }

    // Epilogue
    #pragma unroll
    for (int i = 0; i < 2; ++i) {
        int R0 = m0 + wm + i * 16 + qr;
        #pragma unroll
        for (int j = 0; j < 8; ++j) {
            int C0 = n0 + wn + j * 8 + qc * 2;
            float b0 = bias[C0], b1 = bias[C0 + 1];
            #pragma unroll
            for (int hrow = 0; hrow < 2; ++hrow) {
                int m = R0 + hrow * 8;
                float v0 = acc[i][j][hrow*2 + 0] + b0;
                float v1 = acc[i][j][hrow*2 + 1] + b1;
                if (MODE == 0) {
                    int bb = m >> 11, t = m & (Tt - 1);
                    int which = C0 >> 10, cidx = C0 & 1023;
                    int h = cidx >> 6, dd = cidx & 63;
                    float* dst = (which == 0) ? g_q : (which == 1) ? g_k : g_v;
                    size_t o = (((size_t)(bb*Hh + h))*Tt + t)*HD + dd;
                    dst[o] = v0; dst[o + 1] = v1;     // dd even, same head (HD=64 mult of 8)
                } else {
                    size_t idx = (size_t)m * Cc + C0;
                    out[idx]     = rmask[idx]     ? v0 * KEEP_INV : 0.f;
                    out[idx + 1] = rmask[idx + 1] ? v1 * KEEP_INV : 0.f;
                }
            }
        }
    }
}

// ---------------------------------------------------------------------------
// Flash attention: 64x64 tiles, smem-staged mask, 256-thread softmax.
// ---------------------------------------------------------------------------
#define FLASH_SMEM ((4*64*SQ + 64*64 + 3*64) * 4)
__global__ __launch_bounds__(256) void flash_attn(const unsigned* __restrict__ amask) {
    extern __shared__ float smf[];
    float* Qs = smf;
    float* Ks = Qs + 64*SQ;
    float* Vs = Ks + 64*SQ;
    float* Ss = Vs + 64*SQ;
    unsigned* Ms = (unsigned*)(Ss + 64*SQ);   // [64][64]
    float* m_s  = (float*)(Ms + 64*64);
    float* l_s  = m_s + 64;
    float* al_s = l_s + 64;

    int tid = threadIdx.x;
    int bh = blockIdx.y, qb = blockIdx.x;
    int q0 = qb * 64;
    const float* Qg = g_q + (size_t)bh*Tt*HD;
    const float* Kg = g_k + (size_t)bh*Tt*HD;
    const float* Vg = g_v + (size_t)bh*Tt*HD;

    for (int i = tid; i < 1024; i += 256) {
        int r = i >> 4, c = (i & 15) * 4;
        float4 v = *(const float4*)(Qg + (size_t)(q0 + r)*HD + c);
        Qs[r*SQ+c]   = v.x*0.125f; Qs[r*SQ+c+1] = v.y*0.125f;
        Qs[r*SQ+c+2] = v.z*0.125f; Qs[r*SQ+c+3] = v.w*0.125f;
    }
    if (tid < 64) { m_s[tid] = -INFINITY; l_s[tid] = 0.f; }

    int tr = tid >> 4, tc = tid & 15;
    float acc[4][4] = {};

    for (int kt = 0; kt <= qb; ++kt) {
        int k0 = kt * 64;
        __syncthreads();
        for (int i = tid; i < 1024; i += 256) {
            int r = i >> 4, c = (i & 15) * 4;
            float4 kv = *(const float4*)(Kg + (size_t)(k0 + r)*HD + c);
            Ks[r*SQ+c] = kv.x; Ks[r*SQ+c+1] = kv.y; Ks[r*SQ+c+2] = kv.z; Ks[r*SQ+c+3] = kv.w;
            float4 vv = *(const float4*)(Vg + (size_t)(k0 + r)*HD + c);
            Vs[r*SQ+c] = vv.x; Vs[r*SQ+c+1] = vv.y; Vs[r*SQ+c+2] = vv.z; Vs[r*SQ+c+3] = vv.w;
            *(uint4*)&Ms[r*64 + c] = *(const uint4*)(amask + ((size_t)bh*Tt + q0 + r)*Tt + k0 + c);
        }
        __syncthreads();

        float s[4][4] = {};
        #pragma unroll 8
        for (int d = 0; d < 64; ++d) {
            float a[4], bb[4];
            #pragma unroll
            for (int ii = 0; ii < 4; ++ii) a[ii]  = Qs[(tr*4+ii)*SQ + d];
            #pragma unroll
            for (int jj = 0; jj < 4; ++jj) bb[jj] = Ks[(tc*4+jj)*SQ + d];
            #pragma unroll
            for (int ii = 0; ii < 4; ++ii)
                #pragma unroll
                for (int jj = 0; jj < 4; ++jj)
                    s[ii][jj] = fmaf(a[ii], bb[jj], s[ii][jj]);
        }
        #pragma unroll
        for (int ii = 0; ii < 4; ++ii)
            #pragma unroll
            for (int jj = 0; jj < 4; ++jj) {
                float v = s[ii][jj];
                if (q0 + tr*4 + ii < k0 + tc*4 + jj) v = -INFINITY;
                Ss[(tr*4+ii)*SQ + tc*4+jj] = v;
            }
        __syncthreads();

        // parallel softmax: 4 lanes per row, undropped denominator
        {
            int row = tid >> 2, part = tid & 3, c0 = part * 16;
            float mo = m_s[row];
            float lo = l_s[row];
            __syncwarp();
            float mx = mo;
            #pragma unroll
            for (int j = 0; j < 16; ++j) mx = fmaxf(mx, Ss[row*SQ + c0 + j]);
            mx = fmaxf(mx, __shfl_xor_sync(0xffffffffu, mx, 1));
            mx = fmaxf(mx, __shfl_xor_sync(0xffffffffu, mx, 2));
            float sum = 0.f;
            #pragma unroll
            for (int j = 0; j < 16; ++j) {
                float p = __expf(Ss[row*SQ + c0 + j] - mx);
                sum += p;
                Ss[row*SQ + c0 + j] = Ms[row*64 + c0 + j] ? p * KEEP_INV : 0.f;
            }
            sum += __shfl_xor_sync(0xffffffffu, sum, 1);
            sum += __shfl_xor_sync(0xffffffffu, sum, 2);
            if (part == 0) {
                float al = __expf(mo - mx);
                m_s[row] = mx;
                al_s[row] = al;
                l_s[row] = fmaf(lo, al, sum);
            }
        }
        __syncthreads();

        #pragma unroll
        for (int ii = 0; ii < 4; ++ii) {
            float a = al_s[tr*4+ii];
            #pragma unroll
            for (int dd = 0; dd < 4; ++dd) acc[ii][dd] *= a;
        }
        #pragma unroll 4
        for (int j = 0; j < 64; ++j) {
            float p[4], vv[4];
            #pragma unroll
            for (int ii = 0; ii < 4; ++ii) p[ii]  = Ss[(tr*4+ii)*SQ + j];
            #pragma unroll
            for (int dd = 0; dd < 4; ++dd) vv[dd] = Vs[j*SQ + tc*4+dd];
            #pragma unroll
            for (int ii = 0; ii < 4; ++ii)
                #pragma unroll
                for (int dd = 0; dd < 4; ++dd)
                    acc[ii][dd] = fmaf(p[ii], vv[dd], acc[ii][dd]);
        }
    }

    int b = bh >> 4, h = bh & 15;
    #pragma unroll
    for (int ii = 0; ii < 4; ++ii) {
        int qi = q0 + tr*4 + ii;
        float inv = 1.f / l_s[tr*4+ii];
        #pragma unroll
        for (int dd = 0; dd < 4; ++dd)
            g_y[((size_t)(b*Tt) + qi)*Cc + h*HD + tc*4+dd] = acc[ii][dd]*inv;
    }
}

// ---------------------------------------------------------------------------
extern "C" void kernel_launch(void* const* d_in, const int* in_sizes, int n_in,
                              void* d_out, int out_size) {
    const float* x     = (const float*)d_in[0];
    const float* Wqkv  = (const float*)d_in[1];
    const float* bqkv  = (const float*)d_in[2];
    const float* Wproj = (const float*)d_in[3];
    const float* bproj = (const float*)d_in[4];
    const unsigned* amask = (const unsigned*)d_in[5];
    const unsigned* rmask = (const unsigned*)d_in[6];
    float* out = (float*)d_out;

    cudaFuncSetAttribute(gemm_mma<0>, cudaFuncAttributeMaxDynamicSharedMemorySize, GEMM_SMEM);
    cudaFuncSetAttribute(gemm_mma<1>, cudaFuncAttributeMaxDynamicSharedMemorySize, GEMM_SMEM);
    cudaFuncSetAttribute(flash_attn, cudaFuncAttributeMaxDynamicSharedMemorySize, FLASH_SMEM);

    __nv_bfloat16 *xh, *xl, *wqh, *wql, *wph, *wpl, *yh, *yl;
    float *qy;
    cudaGetSymbolAddress((void**)&xh,  g_xh);  cudaGetSymbolAddress((void**)&xl,  g_xl);
    cudaGetSymbolAddress((void**)&wqh, g_wqh); cudaGetSymbolAddress((void**)&wql, g_wql);
    cudaGetSymbolAddress((void**)&wph, g_wph); cudaGetSymbolAddress((void**)&wpl, g_wpl);
    cudaGetSymbolAddress((void**)&yh,  g_yh);  cudaGetSymbolAddress((void**)&yl,  g_yl);
    cudaGetSymbolAddress((void**)&qy,  g_y);

    cvt_split<<<(NTOK*Cc/4 + 255)/256, 256>>>((const float4*)x, (__nv_bfloat162*)xh, (__nv_bfloat162*)xl, NTOK*Cc/4);
    cvt_split_T<<<dim3(C3/32, Cc/32), dim3(32,8)>>>(Wqkv, wqh, wql, Cc, C3);
    cvt_split_T<<<dim3(Cc/32, Cc/32), dim3(32,8)>>>(Wproj, wph, wpl, Cc, Cc);

    gemm_mma<0><<<dim3(C3/128, NTOK/128), 256, GEMM_SMEM>>>(xh, xl, wqh, wql, bqkv, nullptr, nullptr, Cc);

    flash_attn<<<dim3(Tt/64, Bsz*Hh), 256, FLASH_SMEM>>>(amask);

    cvt_split<<<(NTOK*Cc/4 + 255)/256, 256>>>((const float4*)qy, (__nv_bfloat162*)yh, (__nv_bfloat162*)yl, NTOK*Cc/4);
    gemm_mma<1><<<dim3(Cc/128, NTOK/128), 256, GEMM_SMEM>>>(yh, yl, wph, wpl, bproj, rmask, out, Cc);
}

// round 4
// speedup vs baseline: 3.1221x; 2.0403x over previous
#include <cuda_runtime.h>
#include <cuda_bf16.h>
#include <math.h>
#include <cstdint>

// Problem constants
#define Bsz 2
#define Tt 2048
#define Cc 1024
#define Hh 16
#define HD 64
#define NTOK (Bsz*Tt)   // 4096
#define C3 (3*Cc)       // 3072
#define KEEP_INV (1.0f/0.9f)

// ---------------- scratch (device globals; no allocs allowed) ---------------
__device__ __nv_bfloat16 g_xh[(size_t)NTOK*Cc],  g_xl[(size_t)NTOK*Cc];
__device__ __nv_bfloat16 g_wqh[(size_t)C3*Cc],   g_wql[(size_t)C3*Cc];   // [N,K]
__device__ __nv_bfloat16 g_wph[(size_t)Cc*Cc],   g_wpl[(size_t)Cc*Cc];   // [N,K]
__device__ __nv_bfloat16 g_yh[(size_t)NTOK*Cc],  g_yl[(size_t)NTOK*Cc];
// split q/k: [bh][t][64]; v transposed: [bh][d][t]
__device__ __nv_bfloat16 g_qh[(size_t)32*Tt*HD], g_ql[(size_t)32*Tt*HD];
__device__ __nv_bfloat16 g_kh[(size_t)32*Tt*HD], g_kl[(size_t)32*Tt*HD];
__device__ __nv_bfloat16 g_vth[(size_t)32*HD*Tt], g_vtl[(size_t)32*HD*Tt];

// ---------------- helpers ----------------
__device__ __forceinline__ uint32_t smem_u32(const void* p) {
    uint32_t a;
    asm("{ .reg .u64 t; cvta.to.shared.u64 t, %1; cvt.u32.u64 %0, t; }" : "=r"(a) : "l"(p));
    return a;
}
__device__ __forceinline__ void cp_async16(uint32_t dst, const void* src) {
    asm volatile("cp.async.cg.shared.global [%0], [%1], 16;" :: "r"(dst), "l"(src) : "memory");
}
#define CP_COMMIT() asm volatile("cp.async.commit_group;" ::: "memory")
#define CP_WAIT(n)  asm volatile("cp.async.wait_group %0;" :: "n"(n) : "memory")

__device__ __forceinline__ void mma16816(float* c, const uint32_t* a, const uint32_t* b) {
    asm volatile("mma.sync.aligned.m16n8k16.row.col.f32.bf16.bf16.f32 "
        "{%0,%1,%2,%3}, {%4,%5,%6,%7}, {%8,%9}, {%0,%1,%2,%3};"
        : "+f"(c[0]), "+f"(c[1]), "+f"(c[2]), "+f"(c[3])
        : "r"(a[0]), "r"(a[1]), "r"(a[2]), "r"(a[3]), "r"(b[0]), "r"(b[1]));
}
// pack two floats into hi/lo bf16x2 (split)
__device__ __forceinline__ void split2(float a, float b, uint32_t& hi, uint32_t& lo) {
    __nv_bfloat16 ha = __float2bfloat16(a), hb = __float2bfloat16(b);
    __nv_bfloat162 H(ha, hb);
    hi = *(uint32_t*)&H;
    __nv_bfloat162 L(__float2bfloat16(a - __bfloat162float(ha)),
                     __float2bfloat16(b - __bfloat162float(hb)));
    lo = *(uint32_t*)&L;
}

// ---------------------------------------------------------------------------
// fp32 -> (hi,lo) bf16 split
// ---------------------------------------------------------------------------
__global__ __launch_bounds__(256) void cvt_split(const float4* __restrict__ in,
                                                 __nv_bfloat162* __restrict__ hi,
                                                 __nv_bfloat162* __restrict__ lo,
                                                 int n4) {
    int i = blockIdx.x * 256 + threadIdx.x;
    if (i >= n4) return;
    float4 v = in[i];
    __nv_bfloat16 hx = __float2bfloat16(v.x), hy = __float2bfloat16(v.y);
    __nv_bfloat16 hz = __float2bfloat16(v.z), hw = __float2bfloat16(v.w);
    hi[2*i]   = __nv_bfloat162(hx, hy);
    hi[2*i+1] = __nv_bfloat162(hz, hw);
    lo[2*i]   = __nv_bfloat162(__float2bfloat16(v.x - __bfloat162float(hx)),
                               __float2bfloat16(v.y - __bfloat162float(hy)));
    lo[2*i+1] = __nv_bfloat162(__float2bfloat16(v.z - __bfloat162float(hz)),
                               __float2bfloat16(v.w - __bfloat162float(hw)));
}

// fp32 W[K,N] -> transposed split bf16 [N,K]
__global__ __launch_bounds__(256) void cvt_split_T(const float* __restrict__ in,
                                                   __nv_bfloat16* __restrict__ hi,
                                                   __nv_bfloat16* __restrict__ lo,
                                                   int K, int N) {
    __shared__ float t[32][33];
    int nx = blockIdx.x * 32, kx = blockIdx.y * 32;
    int tx = threadIdx.x, ty = threadIdx.y;  // (32,8)
    #pragma unroll
    for (int r = 0; r < 4; ++r)
        t[ty + 8*r][tx] = in[(size_t)(kx + ty + 8*r) * N + nx + tx];
    __syncthreads();
    #pragma unroll
    for (int r = 0; r < 4; ++r) {
        float v = t[tx][ty + 8*r];
        size_t o = (size_t)(nx + ty + 8*r) * K + kx + tx;
        __nv_bfloat16 h = __float2bfloat16(v);
        hi[o] = h;
        lo[o] = __float2bfloat16(v - __bfloat162float(h));
    }
}

// ---------------------------------------------------------------------------
// mma.sync split-bf16 GEMM: C[M,N] = A[M,K]*B[N,K]^T (+bias, +epilogue)
// MODE 0: qkv -> split q/k ([bh][t][64], q scaled 1/8) and transposed split v.
// MODE 1: proj + resid dropout -> out (fp32).
// ---------------------------------------------------------------------------
#define SR 40
#define TILE_E (128*SR)
#define BUF_E  (4*TILE_E)
#define GEMM_SMEM (2*BUF_E*2)

__device__ __forceinline__ void gemm_issue(uint32_t sb, int buf,
                                           const __nv_bfloat16* Ah, const __nv_bfloat16* Al,
                                           const __nv_bfloat16* Bh, const __nv_bfloat16* Bl,
                                           int m0, int n0, int K, int ch, int tid) {
    #pragma unroll
    for (int it = 0; it < 8; ++it) {
        int u = tid + it * 256;
        int arr = u >> 9;
        int rem = u & 511;
        int row = rem >> 2;
        int c16 = rem & 3;
        const __nv_bfloat16* src = (arr == 0) ? Ah : (arr == 1) ? Al : (arr == 2) ? Bh : Bl;
        int grow = (arr < 2 ? m0 : n0) + row;
        uint32_t soff = (uint32_t)((buf * BUF_E + arr * TILE_E + row * SR + c16 * 8) * 2);
        cp_async16(sb + soff, src + (size_t)grow * K + ch * 32 + c16 * 8);
    }
    CP_COMMIT();
}

template<int MODE>
__global__ __launch_bounds__(256) void gemm_mma(const __nv_bfloat16* __restrict__ Ah,
                                                const __nv_bfloat16* __restrict__ Al,
                                                const __nv_bfloat16* __restrict__ Bh,
                                                const __nv_bfloat16* __restrict__ Bl,
                                                const float* __restrict__ bias,
                                                const unsigned* __restrict__ rmask,
                                                float* __restrict__ out,
                                                int K) {
    extern __shared__ __nv_bfloat16 smg[];
    uint32_t sb = smem_u32(smg);
    int tid = threadIdx.x, wid = tid >> 5, lane = tid & 31;
    int m0 = blockIdx.y * 128, n0 = blockIdx.x * 128;
    int wm = (wid & 3) * 32, wn = (wid >> 2) * 64;
    int qr = lane >> 2, qc = lane & 3;

    float acc[2][8][4] = {};
    int nch = K >> 5;

    gemm_issue(sb, 0, Ah, Al, Bh, Bl, m0, n0, K, 0, tid);

    for (int ch = 0; ch < nch; ++ch) {
        int buf = ch & 1;
        if (ch + 1 < nch) {
            gemm_issue(sb, buf ^ 1, Ah, Al, Bh, Bl, m0, n0, K, ch + 1, tid);
            CP_WAIT(1);
        } else {
            CP_WAIT(0);
        }
        __syncthreads();

        const __nv_bfloat16* sAh = smg + buf * BUF_E;
        const __nv_bfloat16* sAl = sAh + TILE_E;
        const __nv_bfloat16* sBh = sAl + TILE_E;
        const __nv_bfloat16* sBl = sBh + TILE_E;

        #pragma unroll
        for (int ks = 0; ks < 32; ks += 16) {
            uint32_t ah[2][4], al_[2][4];
            #pragma unroll
            for (int i = 0; i < 2; ++i) {
                int r = wm + i * 16 + qr;
                int c = ks + qc * 2;
                ah[i][0]  = *(const uint32_t*)&sAh[r*SR + c];
                ah[i][1]  = *(const uint32_t*)&sAh[(r+8)*SR + c];
                ah[i][2]  = *(const uint32_t*)&sAh[r*SR + c + 8];
                ah[i][3]  = *(const uint32_t*)&sAh[(r+8)*SR + c + 8];
                al_[i][0] = *(const uint32_t*)&sAl[r*SR + c];
                al_[i][1] = *(const uint32_t*)&sAl[(r+8)*SR + c];
                al_[i][2] = *(const uint32_t*)&sAl[r*SR + c + 8];
                al_[i][3] = *(const uint32_t*)&sAl[(r+8)*SR + c + 8];
            }
            #pragma unroll
            for (int j = 0; j < 8; ++j) {
                int n = wn + j * 8 + qr;
                int c = ks + qc * 2;
                uint32_t bh[2], bl[2];
                bh[0] = *(const uint32_t*)&sBh[n*SR + c];
                bh[1] = *(const uint32_t*)&sBh[n*SR + c + 8];
                bl[0] = *(const uint32_t*)&sBl[n*SR + c];
                bl[1] = *(const uint32_t*)&sBl[n*SR + c + 8];
                #pragma unroll
                for (int i = 0; i < 2; ++i) {
                    mma16816(acc[i][j], ah[i], bh);
                    mma16816(acc[i][j], ah[i], bl);
                    mma16816(acc[i][j], al_[i], bh);
                }
            }
        }
        __syncthreads();
    }

    // Epilogue
    #pragma unroll
    for (int i = 0; i < 2; ++i) {
        int R0 = m0 + wm + i * 16 + qr;
        #pragma unroll
        for (int j = 0; j < 8; ++j) {
            int C0 = n0 + wn + j * 8 + qc * 2;
            float b0 = bias[C0], b1 = bias[C0 + 1];
            #pragma unroll
            for (int hrow = 0; hrow < 2; ++hrow) {
                int m = R0 + hrow * 8;
                float v0 = acc[i][j][hrow*2 + 0] + b0;
                float v1 = acc[i][j][hrow*2 + 1] + b1;
                if (MODE == 0) {
                    int bb = m >> 11, t = m & (Tt - 1);
                    int which = C0 >> 10, cidx = C0 & 1023;
                    int h = cidx >> 6, dd = cidx & 63;
                    int bh = bb * Hh + h;
                    if (which == 0) { v0 *= 0.125f; v1 *= 0.125f; }
                    uint32_t hi, lo;
                    split2(v0, v1, hi, lo);
                    if (which == 2) {
                        size_t o0 = ((size_t)bh*HD + dd)*Tt + t;
                        size_t o1 = ((size_t)bh*HD + dd + 1)*Tt + t;
                        __nv_bfloat162 H = *(__nv_bfloat162*)&hi;
                        __nv_bfloat162 L = *(__nv_bfloat162*)&lo;
                        g_vth[o0] = H.x; g_vth[o1] = H.y;
                        g_vtl[o0] = L.x; g_vtl[o1] = L.y;
                    } else {
                        size_t o = ((size_t)bh*Tt + t)*HD + dd;
                        __nv_bfloat16* dh = (which == 0) ? g_qh : g_kh;
                        __nv_bfloat16* dl = (which == 0) ? g_ql : g_kl;
                        *(uint32_t*)&dh[o] = hi;
                        *(uint32_t*)&dl[o] = lo;
                    }
                } else {
                    size_t idx = (size_t)m * Cc + C0;
                    out[idx]     = rmask[idx]     ? v0 * KEEP_INV : 0.f;
                    out[idx + 1] = rmask[idx + 1] ? v1 * KEEP_INV : 0.f;
                }
            }
        }
    }
}

// ---------------------------------------------------------------------------
// Flash attention on HMMA: 128 q-rows per CTA, 64-wide k-tiles,
// 8 warps each owning 16 q-rows x full tile width. Split-bf16 QK and PV.
// ---------------------------------------------------------------------------
#define SRK 72                       // bf16 row stride for 64-col tiles
#define SRM 68                       // uint row stride for mask tile
#define OQH 0
#define OQL (128*SRK*2)              // 18432
#define OB0 (2*128*SRK*2)            // 36864
#define KVB (64*SRK*2)               // 9216
#define OMK (4*KVB)
#define BUFB (4*KVB + 128*SRM*4)     // 71680
#define FLASH_SMEM (OB0 + 2*BUFB)    // 180224

__device__ __forceinline__ void flash_issue(uint32_t sb, char* smem, int buf,
                                            int bh, int q0, int k0,
                                            const unsigned* amask, int tid) {
    // K/V tiles: 4 arrays x 512 16B chunks
    #pragma unroll
    for (int it = 0; it < 8; ++it) {
        int u = tid + it * 256;
        int arr = u >> 9;
        int rem = u & 511;
        int row = rem >> 3;
        int ck = rem & 7;
        const __nv_bfloat16* src;
        size_t g;
        if (arr < 2) {
            src = (arr == 0) ? g_kh : g_kl;
            g = ((size_t)bh*Tt + k0 + row)*HD + ck*8;
        } else {
            src = (arr == 2) ? g_vth : g_vtl;
            g = ((size_t)bh*HD + row)*Tt + k0 + ck*8;
        }
        uint32_t dst = sb + OB0 + buf*BUFB + arr*KVB + (uint32_t)(row*SRK + ck*8)*2;
        cp_async16(dst, src + g);
    }
    // mask tile: 128 rows x 16 chunks
    #pragma unroll
    for (int it = 0; it < 8; ++it) {
        int u = tid + it * 256;
        int row = u >> 4;
        int cu = u & 15;
        const unsigned* src = amask + ((size_t)bh*Tt + q0 + row)*Tt + k0 + cu*4;
        uint32_t dst = sb + OB0 + buf*BUFB + OMK + (uint32_t)(row*SRM*4 + cu*16);
        cp_async16(dst, src);
    }
    CP_COMMIT();
}

__global__ __launch_bounds__(256) void flash_mma(const unsigned* __restrict__ amask) {
    extern __shared__ char smf[];
    uint32_t sb = smem_u32(smf);
    int tid = threadIdx.x, wid = tid >> 5, lane = tid & 31;
    int qr = lane >> 2, qc = lane & 3;
    int bh = blockIdx.y;
    int qb = (gridDim.x - 1) - blockIdx.x;   // big tiles first
    int q0 = qb * 128;
    int nkt = qb * 2 + 2;

    // Q tile load (split): 2 arrays x 1024 chunks
    #pragma unroll
    for (int it = 0; it < 8; ++it) {
        int u = tid + it * 256;
        int arr = u >> 10;
        int rem = u & 1023;
        int row = rem >> 3;
        int ck = rem & 7;
        const __nv_bfloat16* src = arr ? g_ql : g_qh;
        uint32_t dst = sb + (arr ? OQL : OQH) + (uint32_t)(row*SRK + ck*8)*2;
        cp_async16(dst, src + ((size_t)bh*Tt + q0 + row)*HD + ck*8);
    }
    flash_issue(sb, smf, 0, bh, q0, 0, amask, tid);   // commits Q + tile0 together? no:
    // (flash_issue has its own commit; Q chunks were issued before it, so they
    // belong to the same group as tile0 -> completed together at first wait.)

    const __nv_bfloat16* pQh = (const __nv_bfloat16*)(smf + OQH);
    const __nv_bfloat16* pQl = (const __nv_bfloat16*)(smf + OQL);

    int r = wid * 16 + qr;                  // q row within tile
    int rowmax = q0 + wid * 16 + 15;
    float acc[8][4] = {};
    float m0 = -INFINITY, m1 = -INFINITY, l0 = 0.f, l1 = 0.f;

    for (int kt = 0; kt < nkt; ++kt) {
        int buf = kt & 1;
        int k0 = kt * 64;
        if (kt + 1 < nkt) {
            flash_issue(sb, smf, buf ^ 1, bh, q0, (kt+1)*64, amask, tid);
            CP_WAIT(1);
        } else {
            CP_WAIT(0);
        }
        __syncthreads();

        if (k0 <= rowmax) {
            const __nv_bfloat16* pKh = (const __nv_bfloat16*)(smf + OB0 + buf*BUFB);
            const __nv_bfloat16* pKl = pKh + 64*SRK;
            const __nv_bfloat16* pVh = pKl + 64*SRK;
            const __nv_bfloat16* pVl = pVh + 64*SRK;
            const unsigned* pMk = (const unsigned*)(smf + OB0 + buf*BUFB + OMK);

            // ---- S = Q K^T (split 3-term) ----
            float s[8][4] = {};
            #pragma unroll
            for (int ks = 0; ks < 64; ks += 16) {
                int c = ks + qc*2;
                uint32_t ah[4], al[4];
                ah[0] = *(const uint32_t*)&pQh[r*SRK + c];
                ah[1] = *(const uint32_t*)&pQh[(r+8)*SRK + c];
                ah[2] = *(const uint32_t*)&pQh[r*SRK + c + 8];
                ah[3] = *(const uint32_t*)&pQh[(r+8)*SRK + c + 8];
                al[0] = *(const uint32_t*)&pQl[r*SRK + c];
                al[1] = *(const uint32_t*)&pQl[(r+8)*SRK + c];
                al[2] = *(const uint32_t*)&pQl[r*SRK + c + 8];
                al[3] = *(const uint32_t*)&pQl[(r+8)*SRK + c + 8];
                #pragma unroll
                for (int j = 0; j < 8; ++j) {
                    int n = j*8 + qr;
                    uint32_t kb[2], kl[2];
                    kb[0] = *(const uint32_t*)&pKh[n*SRK + c];
                    kb[1] = *(const uint32_t*)&pKh[n*SRK + c + 8];
                    kl[0] = *(const uint32_t*)&pKl[n*SRK + c];
                    kl[1] = *(const uint32_t*)&pKl[n*SRK + c + 8];
                    mma16816(s[j], ah, kb);
                    mma16816(s[j], ah, kl);
                    mma16816(s[j], al, kb);
                }
            }

            // ---- causal mask ----
            int row0 = q0 + r, row1 = row0 + 8;
            #pragma unroll
            for (int j = 0; j < 8; ++j) {
                int cg = k0 + j*8 + qc*2;
                if (cg     > row0) s[j][0] = -INFINITY;
                if (cg + 1 > row0) s[j][1] = -INFINITY;
                if (cg     > row1) s[j][2] = -INFINITY;
                if (cg + 1 > row1) s[j][3] = -INFINITY;
            }

            // ---- online softmax (undropped denominator) ----
            float mx0 = -INFINITY, mx1 = -INFINITY;
            #pragma unroll
            for (int j = 0; j < 8; ++j) {
                mx0 = fmaxf(mx0, fmaxf(s[j][0], s[j][1]));
                mx1 = fmaxf(mx1, fmaxf(s[j][2], s[j][3]));
            }
            mx0 = fmaxf(mx0, __shfl_xor_sync(0xffffffffu, mx0, 1));
            mx0 = fmaxf(mx0, __shfl_xor_sync(0xffffffffu, mx0, 2));
            mx1 = fmaxf(mx1, __shfl_xor_sync(0xffffffffu, mx1, 1));
            mx1 = fmaxf(mx1, __shfl_xor_sync(0xffffffffu, mx1, 2));
            float m0n = fmaxf(m0, mx0), m1n = fmaxf(m1, mx1);
            float a0 = __expf(m0 - m0n), a1 = __expf(m1 - m1n);
            float sum0 = 0.f, sum1 = 0.f;
            int mr0 = (wid*16 + qr) * SRM;
            int mr1 = mr0 + 8*SRM;
            #pragma unroll
            for (int j = 0; j < 8; ++j) {
                uint2 k0m = *(const uint2*)&pMk[mr0 + j*8 + qc*2];
                uint2 k1m = *(const uint2*)&pMk[mr1 + j*8 + qc*2];
                float p0 = __expf(s[j][0] - m0n); sum0 += p0;
                float p1 = __expf(s[j][1] - m0n); sum0 += p1;
                float p2 = __expf(s[j][2] - m1n); sum1 += p2;
                float p3 = __expf(s[j][3] - m1n); sum1 += p3;
                s[j][0] = k0m.x ? p0 * KEEP_INV : 0.f;
                s[j][1] = k0m.y ? p1 * KEEP_INV : 0.f;
                s[j][2] = k1m.x ? p2 * KEEP_INV : 0.f;
                s[j][3] = k1m.y ? p3 * KEEP_INV : 0.f;
            }
            sum0 += __shfl_xor_sync(0xffffffffu, sum0, 1);
            sum0 += __shfl_xor_sync(0xffffffffu, sum0, 2);
            sum1 += __shfl_xor_sync(0xffffffffu, sum1, 1);
            sum1 += __shfl_xor_sync(0xffffffffu, sum1, 2);
            l0 = l0 * a0 + sum0;
            l1 = l1 * a1 + sum1;
            m0 = m0n; m1 = m1n;

            // ---- acc scale + P V (split 3-term, P from registers) ----
            #pragma unroll
            for (int j = 0; j < 8; ++j) {
                acc[j][0] *= a0; acc[j][1] *= a0;
                acc[j][2] *= a1; acc[j][3] *= a1;
            }
            #pragma unroll
            for (int s4 = 0; s4 < 4; ++s4) {
                uint32_t ph[4], pl[4];
                split2(s[2*s4][0],   s[2*s4][1],   ph[0], pl[0]);
                split2(s[2*s4][2],   s[2*s4][3],   ph[1], pl[1]);
                split2(s[2*s4+1][0], s[2*s4+1][1], ph[2], pl[2]);
                split2(s[2*s4+1][2], s[2*s4+1][3], ph[3], pl[3]);
                int cc = s4*16 + qc*2;
                #pragma unroll
                for (int j = 0; j < 8; ++j) {
                    int n = j*8 + qr;
                    uint32_t vb[2], vl[2];
                    vb[0] = *(const uint32_t*)&pVh[n*SRK + cc];
                    vb[1] = *(const uint32_t*)&pVh[n*SRK + cc + 8];
                    vl[0] = *(const uint32_t*)&pVl[n*SRK + cc];
                    vl[1] = *(const uint32_t*)&pVl[n*SRK + cc + 8];
                    mma16816(acc[j], ph, vb);
                    mma16816(acc[j], ph, vl);
                    mma16816(acc[j], pl, vb);
                }
            }
        }
        __syncthreads();
    }

    // ---- epilogue: y = acc / l, write split bf16 [tok][C] ----
    int b = bh >> 4, h = bh & 15;
    float inv0 = 1.f / l0, inv1 = 1.f / l1;
    size_t tok0 = (size_t)b*Tt + q0 + r;
    size_t tok1 = tok0 + 8;
    #pragma unroll
    for (int j = 0; j < 8; ++j) {
        int col = h*HD + j*8 + qc*2;
        uint32_t hi, lo;
        split2(acc[j][0]*inv0, acc[j][1]*inv0, hi, lo);
        *(uint32_t*)&g_yh[tok0*Cc + col] = hi;
        *(uint32_t*)&g_yl[tok0*Cc + col] = lo;
        split2(acc[j][2]*inv1, acc[j][3]*inv1, hi, lo);
        *(uint32_t*)&g_yh[tok1*Cc + col] = hi;
        *(uint32_t*)&g_yl[tok1*Cc + col] = lo;
    }
}

// ---------------------------------------------------------------------------
extern "C" void kernel_launch(void* const* d_in, const int* in_sizes, int n_in,
                              void* d_out, int out_size) {
    const float* x     = (const float*)d_in[0];
    const float* Wqkv  = (const float*)d_in[1];
    const float* bqkv  = (const float*)d_in[2];
    const float* Wproj = (const float*)d_in[3];
    const float* bproj = (const float*)d_in[4];
    const unsigned* amask = (const unsigned*)d_in[5];
    const unsigned* rmask = (const unsigned*)d_in[6];
    float* out = (float*)d_out;

    cudaFuncSetAttribute(gemm_mma<0>, cudaFuncAttributeMaxDynamicSharedMemorySize, GEMM_SMEM);
    cudaFuncSetAttribute(gemm_mma<1>, cudaFuncAttributeMaxDynamicSharedMemorySize, GEMM_SMEM);
    cudaFuncSetAttribute(flash_mma, cudaFuncAttributeMaxDynamicSharedMemorySize, FLASH_SMEM);

    __nv_bfloat16 *xh, *xl, *wqh, *wql, *wph, *wpl, *yh, *yl;
    cudaGetSymbolAddress((void**)&xh,  g_xh);  cudaGetSymbolAddress((void**)&xl,  g_xl);
    cudaGetSymbolAddress((void**)&wqh, g_wqh); cudaGetSymbolAddress((void**)&wql, g_wql);
    cudaGetSymbolAddress((void**)&wph, g_wph); cudaGetSymbolAddress((void**)&wpl, g_wpl);
    cudaGetSymbolAddress((void**)&yh,  g_yh);  cudaGetSymbolAddress((void**)&yl,  g_yl);

    cvt_split<<<(NTOK*Cc/4 + 255)/256, 256>>>((const float4*)x, (__nv_bfloat162*)xh, (__nv_bfloat162*)xl, NTOK*Cc/4);
    cvt_split_T<<<dim3(C3/32, Cc/32), dim3(32,8)>>>(Wqkv, wqh, wql, Cc, C3);
    cvt_split_T<<<dim3(Cc/32, Cc/32), dim3(32,8)>>>(Wproj, wph, wpl, Cc, Cc);

    gemm_mma<0><<<dim3(C3/128, NTOK/128), 256, GEMM_SMEM>>>(xh, xl, wqh, wql, bqkv, nullptr, nullptr, Cc);

    flash_mma<<<dim3(Tt/128, Bsz*Hh), 256, FLASH_SMEM>>>(amask);

    gemm_mma<1><<<dim3(Cc/128, NTOK/128), 256, GEMM_SMEM>>>(yh, yl, wph, wpl, bproj, rmask, out, Cc);
}